// round 10
// baseline (speedup 1.0000x reference)
#include <cuda_runtime.h>
#include <cstdint>

// Fixed problem: n=4, c=16, h=w=64, patch=3
#define NB 4
#define CH 16
#define W 64
#define HW 4096
#define RST 67            // Rbuf row stride (67 % 32 = 3 -> conflict-free cols)
#define ABST 68           // A/B buffer row stride (float2-aligned)
#define NSTG 1122         // 17 rows x 66 staged values per operand

#define CY(v) (min(max((v), 0), 63))

__device__ float g_eS[NB * HW];
__device__ float g_eT[NB * HW];
__device__ unsigned long long g_best[NB * HW];

// ---------------------------------------------------------------------------
// Per-pixel channel sum of squares (eS / eT); y==0 also resets g_best.
// ---------------------------------------------------------------------------
__global__ void norm1_kernel(const float* __restrict__ s, const float* __restrict__ t) {
    int idx = blockIdx.x * blockDim.x + threadIdx.x;
    if (idx >= NB * HW) return;
    const float* src = blockIdx.y ? t : s;
    int b = idx >> 12, pix = idx & (HW - 1);
    float acc = 0.f;
#pragma unroll
    for (int c = 0; c < CH; c++) {
        float v = src[((size_t)(b * CH + c) << 12) + pix];
        acc = fmaf(v, v, acc);
    }
    if (blockIdx.y) {
        g_eT[idx] = acc;
    } else {
        g_eS[idx] = acc;
        g_best[idx] = ~0ull;
    }
}

// ---------------------------------------------------------------------------
// Diagonal sweep kernel. Block = (batch b, pair slot i): runs diagonals
// kk = i and kk = 126 - i (steps 66-ceil(kk/2) each; sums ~69 -> balanced).
// R~(p, p+d)(ix~, jx~) is a K=18 GEMM folding both norms:
//   ch 0..15: (-2 s[c][CY(p-1)][CY(ix~-1)]) * t[c][CY(p+d-1)][CY(jx~-1)]
//   ch 16   : eS~(p, ix~) * 1
//   ch 17   : 1 * eT~(p+d, jx~)
// d2(iy, jy=iy+d)(ix,jx) = sum_uy Gx(p=iy+uy), Gx = diag-x-stencil of R~.
// Finished rows merged via global atomicMin on packed key (d2bits<<12 | j).
// ---------------------------------------------------------------------------
__global__ __launch_bounds__(256, 2) void nn_kernel(const float* __restrict__ s,
                                                    const float* __restrict__ t) {
    __shared__ float Abuf[18 * ABST];
    __shared__ float Bbuf[18 * ABST];
    __shared__ float Rbuf[66 * RST];
    __shared__ unsigned long long bm[4 * 64];

    const int tid = threadIdx.x;
    const int blk = blockIdx.x;
    const int i = blk >> 2;             // pair slot 0..63
    const int b = blk & 3;

    const float* sB = s + ((size_t)b * CH << 12);
    const float* tB = t + ((size_t)b * CH << 12);
    const float* eSb = g_eS + b * HW;
    const float* eTb = g_eT + b * HW;

    // ---- staging precompute (task-independent): 5 (A,B) elems/thread ----
    const float* pA[5]; const float* pB[5];
    float wA[5]; unsigned dA[5], dB[5]; bool val[5];
#pragma unroll
    for (int q = 0; q < 5; q++) {
        int u = tid + 256 * q;
        val[q] = (u < NSTG);
        int uu = val[q] ? u : 0;
        int m = uu / 66, xx = uu - 66 * m;
        int gx = CY(xx - 1);
        if (m < 16) { pA[q] = sB + (m << 12) + gx; wA[q] = -2.f; }
        else        { pA[q] = eSb + gx;            wA[q] = 1.f;  }
        dA[q] = m * ABST + xx;
        if (m < 16) pB[q] = tB + (m << 12) + gx;
        else        pB[q] = eTb + gx;
        dB[q] = ((m == 16) ? 17 : m) * ABST + xx;
    }
    // constant channels: A ch17 = 1, B ch16 = 1
    if (tid < 66) {
        Abuf[17 * ABST + tid] = 1.f;
        Bbuf[16 * ABST + tid] = 1.f;
    }

    // GEMM fragment mapping: 242 active threads, 3 ix~ x 6 jx~ each
    const bool act = tid < 242;
    const int ti = act ? (tid / 11) : 0;
    const int tj = act ? (tid - 11 * ti) : 0;

    // epilogue mapping: query ix = eix, jx band = 16*eg
    const int eix = tid & 63;
    const int eg = tid >> 6;
    const int ejx0 = eg << 4;
    const float* R0 = Rbuf + eix * RST + ejx0;
    const float* R1 = Rbuf + (eix + 1) * RST + ejx0 + 1;
    const float* R2 = Rbuf + (eix + 2) * RST + ejx0 + 2;

    for (int task = 0; task < 2; task++) {
        const int kk = task ? (126 - i) : i;
        if (task && kk == i) break;     // singleton middle diagonal
        const int d = (kk == 0) ? 0 : ((kk & 1) ? ((kk + 1) >> 1) : -(kk >> 1));
        const int lo = max(0, -d);
        const int steps = 66 - abs(d);

        float rA[5], rB[5];
        // first loads (p = lo)
        {
            int ra = CY(lo - 1) * W, rb = CY(lo + d - 1) * W;
#pragma unroll
            for (int q = 0; q < 5; q++) if (val[q]) {
                rA[q] = __ldg(pA[q] + ra);
                rB[q] = __ldg(pB[q] + rb);
            }
        }

        float A1[16], A2[16];
#pragma unroll
        for (int jj = 0; jj < 16; jj++) { A1[jj] = 0.f; A2[jj] = 0.f; }

        for (int ss = 0; ss < steps; ss++) {
            // (1) store staged operands
#pragma unroll
            for (int q = 0; q < 5; q++) if (val[q]) {
                Abuf[dA[q]] = rA[q] * wA[q];
                Bbuf[dB[q]] = rB[q];
            }
            __syncthreads();                          // (a)

            // (2) prefetch next row pair
            if (ss + 1 < steps) {
                int pn = lo + ss + 1;
                int ra = CY(pn - 1) * W, rb = CY(pn + d - 1) * W;
#pragma unroll
                for (int q = 0; q < 5; q++) if (val[q]) {
                    rA[q] = __ldg(pA[q] + ra);
                    rB[q] = __ldg(pB[q] + rb);
                }
            }

            // (3) K=18 GEMM -> R~ tile
            if (act) {
                float acc[3][6];
#pragma unroll
                for (int m = 0; m < 3; m++)
#pragma unroll
                    for (int n = 0; n < 6; n++) acc[m][n] = 0.f;
                const float* Ap = Abuf + 3 * ti;
                const float* Bp = Bbuf + 6 * tj;
#pragma unroll 6
                for (int k = 0; k < 18; k++) {
                    float a0 = Ap[k * ABST], a1 = Ap[k * ABST + 1], a2 = Ap[k * ABST + 2];
                    float2 b0 = *(const float2*)(Bp + k * ABST);
                    float2 b1 = *(const float2*)(Bp + k * ABST + 2);
                    float2 b2 = *(const float2*)(Bp + k * ABST + 4);
                    acc[0][0] = fmaf(a0, b0.x, acc[0][0]);
                    acc[0][1] = fmaf(a0, b0.y, acc[0][1]);
                    acc[0][2] = fmaf(a0, b1.x, acc[0][2]);
                    acc[0][3] = fmaf(a0, b1.y, acc[0][3]);
                    acc[0][4] = fmaf(a0, b2.x, acc[0][4]);
                    acc[0][5] = fmaf(a0, b2.y, acc[0][5]);
                    acc[1][0] = fmaf(a1, b0.x, acc[1][0]);
                    acc[1][1] = fmaf(a1, b0.y, acc[1][1]);
                    acc[1][2] = fmaf(a1, b1.x, acc[1][2]);
                    acc[1][3] = fmaf(a1, b1.y, acc[1][3]);
                    acc[1][4] = fmaf(a1, b2.x, acc[1][4]);
                    acc[1][5] = fmaf(a1, b2.y, acc[1][5]);
                    acc[2][0] = fmaf(a2, b0.x, acc[2][0]);
                    acc[2][1] = fmaf(a2, b0.y, acc[2][1]);
                    acc[2][2] = fmaf(a2, b1.x, acc[2][2]);
                    acc[2][3] = fmaf(a2, b1.y, acc[2][3]);
                    acc[2][4] = fmaf(a2, b2.x, acc[2][4]);
                    acc[2][5] = fmaf(a2, b2.y, acc[2][5]);
                }
#pragma unroll
                for (int m = 0; m < 3; m++)
#pragma unroll
                    for (int n = 0; n < 6; n++)
                        Rbuf[(3 * ti + m) * RST + 6 * tj + n] = acc[m][n];
            }
            __syncthreads();                          // (b)

            // (4) epilogue: diag-x-stencil, sliding window, argmin on finish
            const bool fin = (ss >= 2);
            const int jy = lo + ss - 2 + d;
            unsigned long long cand = ~0ull;
            const unsigned jrow = (unsigned)(jy * W + ejx0);
#pragma unroll
            for (int jj = 0; jj < 16; jj++) {
                float g = R0[jj] + R1[jj] + R2[jj];
                if (fin) {
                    float d2 = A2[jj] + g;
                    unsigned long long key =
                        ((unsigned long long)__float_as_uint(d2) << 12) | (jrow + jj);
                    cand = key < cand ? key : cand;
                }
                A2[jj] = A1[jj] + g;
                A1[jj] = g;
            }
            if (fin) bm[(eg << 6) + eix] = cand;
            __syncthreads();                          // (c)

            if (fin && tid < 64) {
                unsigned long long m0 = bm[tid];
                unsigned long long m1 = bm[64 + tid];
                unsigned long long m2 = bm[128 + tid];
                unsigned long long m3 = bm[192 + tid];
                m0 = m1 < m0 ? m1 : m0;
                m2 = m3 < m2 ? m3 : m2;
                m0 = m2 < m0 ? m2 : m0;
                int iy = lo + ss - 2;
                atomicMin(&g_best[b * HW + iy * W + tid], m0);
            }
        }
        __syncthreads();   // task boundary: staging of next task vs GEMM reads
    }
}

// ---------------------------------------------------------------------------
// Decode packed keys -> (jy, jx, d2).
// ---------------------------------------------------------------------------
__global__ void reduce_kernel(float* __restrict__ out) {
    int idx = blockIdx.x * blockDim.x + threadIdx.x;
    if (idx >= NB * HW) return;
    int b = idx >> 12, q = idx & (HW - 1);
    unsigned long long best = g_best[idx];
    int j = (int)(best & 4095u);
    float d2 = __uint_as_float((unsigned)(best >> 12));
    out[(size_t)b * 2 * HW + q]                    = (float)(j >> 6);
    out[(size_t)b * 2 * HW + HW + q]               = (float)(j & 63);
    out[(size_t)NB * 2 * HW + (size_t)b * HW + q]  = d2;
}

extern "C" void kernel_launch(void* const* d_in, const int* in_sizes, int n_in,
                              void* d_out, int out_size) {
    const float* s = (const float*)d_in[0];
    const float* t = (const float*)d_in[1];
    float* out = (float*)d_out;

    norm1_kernel<<<dim3((NB * HW + 255) / 256, 2), 256>>>(s, t);
    nn_kernel<<<64 * NB, 256>>>(s, t);
    reduce_kernel<<<(NB * HW + 255) / 256, 256>>>(out);
}

// round 11
// speedup vs baseline: 1.1209x; 1.1209x over previous
#include <cuda_runtime.h>
#include <cstdint>

// Fixed problem: n=4, c=16, h=w=64, patch=3
#define NB 4
#define CH 16
#define W 64
#define HW 4096
#define NDIAG 127
#define RST 67            // Rbuf row stride (67 % 32 = 3 -> conflict-free cols)
#define ABST 68           // A/B buffer row stride (float2-aligned)
#define NSTG 1122         // 17 rows x 66 staged values per operand

#define CY(v) (min(max((v), 0), 63))

__device__ float g_eS[NB * HW];
__device__ float g_eT[NB * HW];
__device__ unsigned long long g_best[NB * HW];

// ---------------------------------------------------------------------------
// Per-pixel channel sum of squares (eS / eT); y==0 also resets g_best.
// ---------------------------------------------------------------------------
__global__ void norm1_kernel(const float* __restrict__ s, const float* __restrict__ t) {
    int idx = blockIdx.x * blockDim.x + threadIdx.x;
    if (idx >= NB * HW) return;
    const float* src = blockIdx.y ? t : s;
    int b = idx >> 12, pix = idx & (HW - 1);
    float acc = 0.f;
#pragma unroll
    for (int c = 0; c < CH; c++) {
        float v = src[((size_t)(b * CH + c) << 12) + pix];
        acc = fmaf(v, v, acc);
    }
    if (blockIdx.y) {
        g_eT[idx] = acc;
    } else {
        g_eS[idx] = acc;
        g_best[idx] = ~0ull;
    }
}

// ---------------------------------------------------------------------------
// Diagonal sweep kernel. Block = (batch b, diagonal d = jy - iy), 508 blocks.
// R~(p, p+d)(ix~, jx~) is a K=18 GEMM folding both norms:
//   ch 0..15: (-2 s[c][CY(p-1)][CY(ix~-1)]) * t[c][CY(p+d-1)][CY(jx~-1)]
//   ch 16   : eS~(p, ix~) * 1
//   ch 17   : 1 * eT~(p+d, jx~)
// d2(iy, jy=iy+d)(ix,jx) = sum_uy Gx(p=iy+uy), Gx = diag-x-stencil of R~.
// Two syncs per step: staging is double-buffered; argmin merges straight to
// global via atomicMin on packed key (d2bits<<12 | j) = first occurrence.
// ---------------------------------------------------------------------------
__global__ __launch_bounds__(256, 2) void nn_kernel(const float* __restrict__ s,
                                                    const float* __restrict__ t) {
    __shared__ float Abuf[2][18 * ABST];
    __shared__ float Bbuf[2][18 * ABST];
    __shared__ float Rbuf[66 * RST];

    const int tid = threadIdx.x;
    const int blk = blockIdx.x;
    const int kk = blk >> 2;            // diagonal index 0..126 (|d| ascending)
    const int b = blk & 3;
    const int d = (kk == 0) ? 0 : ((kk & 1) ? ((kk + 1) >> 1) : -(kk >> 1));
    const int lo = max(0, -d);
    const int steps = 66 - abs(d);

    const float* sB = s + ((size_t)b * CH << 12);
    const float* tB = t + ((size_t)b * CH << 12);
    const float* eSb = g_eS + b * HW;
    const float* eTb = g_eT + b * HW;

    // ---- staging precompute: 5 (A,B) elements per thread ----
    const float* pA[5]; const float* pB[5];
    float wA[5]; unsigned dA[5], dB[5]; bool val[5];
    float rA[5], rB[5];
#pragma unroll
    for (int q = 0; q < 5; q++) {
        int u = tid + 256 * q;
        val[q] = (u < NSTG);
        int uu = val[q] ? u : 0;
        int m = uu / 66, xx = uu - 66 * m;
        int gx = CY(xx - 1);
        if (m < 16) { pA[q] = sB + (m << 12) + gx; wA[q] = -2.f; }
        else        { pA[q] = eSb + gx;            wA[q] = 1.f;  }
        dA[q] = m * ABST + xx;
        if (m < 16) pB[q] = tB + (m << 12) + gx;
        else        pB[q] = eTb + gx;
        dB[q] = ((m == 16) ? 17 : m) * ABST + xx;
    }
    // constant channels in both buffers: A ch17 = 1, B ch16 = 1
    if (tid < 66) {
        Abuf[0][17 * ABST + tid] = 1.f;
        Abuf[1][17 * ABST + tid] = 1.f;
        Bbuf[0][16 * ABST + tid] = 1.f;
        Bbuf[1][16 * ABST + tid] = 1.f;
    }

    // prologue: stage p = lo into buf0, prefetch p = lo+1 into regs
    {
        int ra = CY(lo - 1) * W, rb = CY(lo + d - 1) * W;
#pragma unroll
        for (int q = 0; q < 5; q++) if (val[q]) {
            Abuf[0][dA[q]] = __ldg(pA[q] + ra) * wA[q];
            Bbuf[0][dB[q]] = __ldg(pB[q] + rb);
        }
        if (steps > 1) {
            int ra1 = CY(lo) * W, rb1 = CY(lo + d) * W;
#pragma unroll
            for (int q = 0; q < 5; q++) if (val[q]) {
                rA[q] = __ldg(pA[q] + ra1);
                rB[q] = __ldg(pB[q] + rb1);
            }
        }
    }

    // GEMM fragment mapping: 242 active threads, 3 ix~ x 6 jx~ each
    const bool act = tid < 242;
    const int ti = act ? (tid / 11) : 0;
    const int tj = act ? (tid - 11 * ti) : 0;

    // epilogue mapping: query ix = eix, jx band = 16*eg
    const int eix = tid & 63;
    const int eg = tid >> 6;
    const int ejx0 = eg << 4;
    const float* R0 = Rbuf + eix * RST + ejx0;
    const float* R1 = Rbuf + (eix + 1) * RST + ejx0 + 1;
    const float* R2 = Rbuf + (eix + 2) * RST + ejx0 + 2;
    unsigned long long* gb = g_best + b * HW + eix;

    float A1[16], A2[16];
#pragma unroll
    for (int jj = 0; jj < 16; jj++) { A1[jj] = 0.f; A2[jj] = 0.f; }

    for (int ss = 0; ss < steps; ss++) {
        const int cur = ss & 1;
        __syncthreads();   // buf[cur] stores visible; prev epilogue done w/ Rbuf

        // ---- K=18 GEMM from buf[cur] -> R~ tile ----
        if (act) {
            float acc[3][6];
#pragma unroll
            for (int m = 0; m < 3; m++)
#pragma unroll
                for (int n = 0; n < 6; n++) acc[m][n] = 0.f;
            const float* Ap = Abuf[cur] + 3 * ti;
            const float* Bp = Bbuf[cur] + 6 * tj;
#pragma unroll 6
            for (int k = 0; k < 18; k++) {
                float a0 = Ap[k * ABST], a1 = Ap[k * ABST + 1], a2 = Ap[k * ABST + 2];
                float2 b0 = *(const float2*)(Bp + k * ABST);
                float2 b1 = *(const float2*)(Bp + k * ABST + 2);
                float2 b2 = *(const float2*)(Bp + k * ABST + 4);
                acc[0][0] = fmaf(a0, b0.x, acc[0][0]);
                acc[0][1] = fmaf(a0, b0.y, acc[0][1]);
                acc[0][2] = fmaf(a0, b1.x, acc[0][2]);
                acc[0][3] = fmaf(a0, b1.y, acc[0][3]);
                acc[0][4] = fmaf(a0, b2.x, acc[0][4]);
                acc[0][5] = fmaf(a0, b2.y, acc[0][5]);
                acc[1][0] = fmaf(a1, b0.x, acc[1][0]);
                acc[1][1] = fmaf(a1, b0.y, acc[1][1]);
                acc[1][2] = fmaf(a1, b1.x, acc[1][2]);
                acc[1][3] = fmaf(a1, b1.y, acc[1][3]);
                acc[1][4] = fmaf(a1, b2.x, acc[1][4]);
                acc[1][5] = fmaf(a1, b2.y, acc[1][5]);
                acc[2][0] = fmaf(a2, b0.x, acc[2][0]);
                acc[2][1] = fmaf(a2, b0.y, acc[2][1]);
                acc[2][2] = fmaf(a2, b1.x, acc[2][2]);
                acc[2][3] = fmaf(a2, b1.y, acc[2][3]);
                acc[2][4] = fmaf(a2, b2.x, acc[2][4]);
                acc[2][5] = fmaf(a2, b2.y, acc[2][5]);
            }
#pragma unroll
            for (int m = 0; m < 3; m++)
#pragma unroll
                for (int n = 0; n < 6; n++)
                    Rbuf[(3 * ti + m) * RST + 6 * tj + n] = acc[m][n];
        }

        // ---- stage next row pair into buf[cur^1]; prefetch the one after ----
        if (ss + 1 < steps) {
#pragma unroll
            for (int q = 0; q < 5; q++) if (val[q]) {
                Abuf[cur ^ 1][dA[q]] = rA[q] * wA[q];
                Bbuf[cur ^ 1][dB[q]] = rB[q];
            }
        }
        if (ss + 2 < steps) {
            int pn = lo + ss + 2;
            int ra = CY(pn - 1) * W, rb = CY(pn + d - 1) * W;
#pragma unroll
            for (int q = 0; q < 5; q++) if (val[q]) {
                rA[q] = __ldg(pA[q] + ra);
                rB[q] = __ldg(pB[q] + rb);
            }
        }
        __syncthreads();   // Rbuf writes visible

        // ---- epilogue: diag-x-stencil, sliding window, argmin on finish ----
        const bool fin = (ss >= 2);
        const int jy = lo + ss - 2 + d;
        unsigned long long cand = ~0ull;
        const unsigned jrow = (unsigned)(jy * W + ejx0);
#pragma unroll
        for (int jj = 0; jj < 16; jj++) {
            float g = R0[jj] + R1[jj] + R2[jj];
            if (fin) {
                float d2 = A2[jj] + g;
                unsigned long long key =
                    ((unsigned long long)__float_as_uint(d2) << 12) | (jrow + jj);
                cand = key < cand ? key : cand;
            }
            A2[jj] = A1[jj] + g;
            A1[jj] = g;
        }
        if (fin) {
            int iy = lo + ss - 2;
            atomicMin(gb + iy * W, cand);
        }
    }
}

// ---------------------------------------------------------------------------
// Decode packed keys -> (jy, jx, d2).
// ---------------------------------------------------------------------------
__global__ void reduce_kernel(float* __restrict__ out) {
    int idx = blockIdx.x * blockDim.x + threadIdx.x;
    if (idx >= NB * HW) return;
    int b = idx >> 12, q = idx & (HW - 1);
    unsigned long long best = g_best[idx];
    int j = (int)(best & 4095u);
    float d2 = __uint_as_float((unsigned)(best >> 12));
    out[(size_t)b * 2 * HW + q]                    = (float)(j >> 6);
    out[(size_t)b * 2 * HW + HW + q]               = (float)(j & 63);
    out[(size_t)NB * 2 * HW + (size_t)b * HW + q]  = d2;
}

extern "C" void kernel_launch(void* const* d_in, const int* in_sizes, int n_in,
                              void* d_out, int out_size) {
    const float* s = (const float*)d_in[0];
    const float* t = (const float*)d_in[1];
    float* out = (float*)d_out;

    norm1_kernel<<<dim3((NB * HW + 255) / 256, 2), 256>>>(s, t);
    nn_kernel<<<NDIAG * NB, 256>>>(s, t);
    reduce_kernel<<<(NB * HW + 255) / 256, 256>>>(out);
}